// round 14
// baseline (speedup 1.0000x reference)
#include <cuda_runtime.h>

#define N   512
#define DIM 384
#define BK  32
#define KSPLIT 192      // per-group K range
#define NT  6           // KSPLIT / BK tiles per group

// Scratch (device globals per allocation-free rule)
__device__ float    g_D[N * N];    // pairwise distances, diag = 1e6
__device__ float    g_prec[N];     // per-query soft precision
__device__ unsigned g_ctr;         // monotonic ticket (replay-safe)

// Branchless full-range sigmoid (exp underflow -> exact 0/1 saturation)
__device__ __forceinline__ float sigmoid_nb(float x) {
    float e = __expf(-fabsf(x));
    float p = __fdividef(1.f, 1.f + e);
    return (x >= 0.f) ? p : 1.f - p;
}

// ---------------- Kernel 1: Gram -> distance, split-K, 256 threads ----------------
// Tile 32(q) x 64(m), grid 128. Group g (t>>7) covers k in [192g, 192g+192).
// Per-thread 4x4 micro-tile: 2 B LDS per FMA (crossbar/FFMA balanced), 8 warps.
#define SA_STR 36   // 144 B rows: 16B-aligned
#define SB_STR 68   // 272 B rows: 16B-aligned

__global__ void __launch_bounds__(256, 1) k_gram(const float* __restrict__ emb) {
    __shared__ __align__(16) float sa[2][BK * SA_STR];   // per-group A tile
    __shared__ __align__(16) float sb[2][BK * SB_STR];   // per-group B tile
    __shared__ float snA2[2][32];
    __shared__ float snB2[2][64];
    __shared__ __align__(16) float accbuf[128 * 16];     // group1 -> group0 spill

    const int t  = threadIdx.x;
    const int g  = t >> 7;            // warp-group 0/1
    const int u  = t & 127;           // id within group
    const int q0 = (blockIdx.x >> 3) * 32;
    const int m0 = (blockIdx.x & 7) * 64;
    const int ty = u >> 4;            // 0..7  -> 4 q-rows at ty*4
    const int tx = u & 15;            // 0..15 -> 4 m-cols at tx*4
    const int arow = u >> 3, ac4 = u & 7;
    const int kb = g * KSPLIT;

    const float* pa0 = emb + (size_t)(q0 + arow)      * DIM + kb + ac4 * 4;
    const float* pa1 = emb + (size_t)(q0 + arow + 16) * DIM + kb + ac4 * 4;
    const float* pb[4];
#pragma unroll
    for (int i = 0; i < 4; i++)
        pb[i] = emb + (size_t)(m0 + arow + 16 * i) * DIM + kb + ac4 * 4;

    float acc[4][4];
#pragma unroll
    for (int i = 0; i < 4; i++)
#pragma unroll
        for (int j = 0; j < 4; j++) acc[i][j] = 0.f;
    float nA0 = 0.f, nA1 = 0.f;
    float nB[4] = {0.f, 0.f, 0.f, 0.f};

    float* mysa = sa[g];
    float* mysb = sb[g];

    float4 ra0, ra1, rb[4];
    ra0 = *(const float4*)pa0;
    ra1 = *(const float4*)pa1;
#pragma unroll
    for (int i = 0; i < 4; i++) rb[i] = *(const float4*)pb[i];

#pragma unroll
    for (int e = 0; e < 4; e++) {
        mysa[(ac4 * 4 + e) * SA_STR + arow]      = ((const float*)&ra0)[e];
        mysa[(ac4 * 4 + e) * SA_STR + arow + 16] = ((const float*)&ra1)[e];
#pragma unroll
        for (int i = 0; i < 4; i++)
            mysb[(ac4 * 4 + e) * SB_STR + arow + 16 * i] = ((const float*)&rb[i])[e];
    }
    nA0 = fmaf(ra0.x,ra0.x,fmaf(ra0.y,ra0.y,fmaf(ra0.z,ra0.z,fmaf(ra0.w,ra0.w,nA0))));
    nA1 = fmaf(ra1.x,ra1.x,fmaf(ra1.y,ra1.y,fmaf(ra1.z,ra1.z,fmaf(ra1.w,ra1.w,nA1))));
#pragma unroll
    for (int i = 0; i < 4; i++)
        nB[i] = fmaf(rb[i].x,rb[i].x,fmaf(rb[i].y,rb[i].y,fmaf(rb[i].z,rb[i].z,fmaf(rb[i].w,rb[i].w,nB[i]))));
    __syncthreads();

#pragma unroll 1
    for (int tt = 0; tt < NT; tt++) {
        if (tt + 1 < NT) {   // prefetch next tile into registers
            const int ko = (tt + 1) * BK;
            ra0 = *(const float4*)(pa0 + ko);
            ra1 = *(const float4*)(pa1 + ko);
#pragma unroll
            for (int i = 0; i < 4; i++) rb[i] = *(const float4*)(pb[i] + ko);
        }

#pragma unroll
        for (int k = 0; k < BK; k++) {
            float4 av = *(const float4*)&mysa[k * SA_STR + ty * 4];
            float4 bv = *(const float4*)&mysb[k * SB_STR + tx * 4];
            acc[0][0] = fmaf(av.x, bv.x, acc[0][0]);
            acc[0][1] = fmaf(av.x, bv.y, acc[0][1]);
            acc[0][2] = fmaf(av.x, bv.z, acc[0][2]);
            acc[0][3] = fmaf(av.x, bv.w, acc[0][3]);
            acc[1][0] = fmaf(av.y, bv.x, acc[1][0]);
            acc[1][1] = fmaf(av.y, bv.y, acc[1][1]);
            acc[1][2] = fmaf(av.y, bv.z, acc[1][2]);
            acc[1][3] = fmaf(av.y, bv.w, acc[1][3]);
            acc[2][0] = fmaf(av.z, bv.x, acc[2][0]);
            acc[2][1] = fmaf(av.z, bv.y, acc[2][1]);
            acc[2][2] = fmaf(av.z, bv.z, acc[2][2]);
            acc[2][3] = fmaf(av.z, bv.w, acc[2][3]);
            acc[3][0] = fmaf(av.w, bv.x, acc[3][0]);
            acc[3][1] = fmaf(av.w, bv.y, acc[3][1]);
            acc[3][2] = fmaf(av.w, bv.z, acc[3][2]);
            acc[3][3] = fmaf(av.w, bv.w, acc[3][3]);
        }

        if (tt + 1 < NT) {
            __syncthreads();   // all reads of current tile done
#pragma unroll
            for (int e = 0; e < 4; e++) {
                mysa[(ac4 * 4 + e) * SA_STR + arow]      = ((const float*)&ra0)[e];
                mysa[(ac4 * 4 + e) * SA_STR + arow + 16] = ((const float*)&ra1)[e];
#pragma unroll
                for (int i = 0; i < 4; i++)
                    mysb[(ac4 * 4 + e) * SB_STR + arow + 16 * i] = ((const float*)&rb[i])[e];
            }
            nA0 = fmaf(ra0.x,ra0.x,fmaf(ra0.y,ra0.y,fmaf(ra0.z,ra0.z,fmaf(ra0.w,ra0.w,nA0))));
            nA1 = fmaf(ra1.x,ra1.x,fmaf(ra1.y,ra1.y,fmaf(ra1.z,ra1.z,fmaf(ra1.w,ra1.w,nA1))));
#pragma unroll
            for (int i = 0; i < 4; i++)
                nB[i] = fmaf(rb[i].x,rb[i].x,fmaf(rb[i].y,rb[i].y,fmaf(rb[i].z,rb[i].z,fmaf(rb[i].w,rb[i].w,nB[i]))));
            __syncthreads();   // new tile visible
        }
    }

    // partial norms: 8 k-chunk threads per row share u>>3 -> xor 1,2,4 in-warp
    nA0 += __shfl_xor_sync(0xffffffffu, nA0, 1);
    nA0 += __shfl_xor_sync(0xffffffffu, nA0, 2);
    nA0 += __shfl_xor_sync(0xffffffffu, nA0, 4);
    nA1 += __shfl_xor_sync(0xffffffffu, nA1, 1);
    nA1 += __shfl_xor_sync(0xffffffffu, nA1, 2);
    nA1 += __shfl_xor_sync(0xffffffffu, nA1, 4);
#pragma unroll
    for (int i = 0; i < 4; i++) {
        nB[i] += __shfl_xor_sync(0xffffffffu, nB[i], 1);
        nB[i] += __shfl_xor_sync(0xffffffffu, nB[i], 2);
        nB[i] += __shfl_xor_sync(0xffffffffu, nB[i], 4);
    }
    if (ac4 == 0) {
        snA2[g][arow]      = nA0;
        snA2[g][arow + 16] = nA1;
#pragma unroll
        for (int i = 0; i < 4; i++) snB2[g][arow + 16 * i] = nB[i];
    }
    __syncthreads();

    // group 1 spills accumulators; group 0 combines and writes distances
    if (g == 1) {
#pragma unroll
        for (int i = 0; i < 4; i++)
            *(float4*)&accbuf[u * 16 + i * 4] =
                make_float4(acc[i][0], acc[i][1], acc[i][2], acc[i][3]);
    }
    __syncthreads();

    if (g == 0) {
#pragma unroll
        for (int i = 0; i < 4; i++) {
            float4 o = *(const float4*)&accbuf[u * 16 + i * 4];
            acc[i][0] += o.x; acc[i][1] += o.y; acc[i][2] += o.z; acc[i][3] += o.w;
        }
#pragma unroll
        for (int i = 0; i < 4; i++) {
            const int q  = q0 + ty * 4 + i;
            const int mb = m0 + tx * 4;
            const float nq = snA2[0][ty * 4 + i] + snA2[1][ty * 4 + i];
            float dv[4];
#pragma unroll
            for (int c = 0; c < 4; c++) {
                float nm = snB2[0][tx * 4 + c] + snB2[1][tx * 4 + c];
                float d2 = nq + nm - 2.f * acc[i][c];
                dv[c] = (q == mb + c) ? 1e6f : sqrtf(fmaxf(d2, 1e-12f));
            }
            *(float4*)&g_D[(size_t)q * N + mb] = make_float4(dv[0], dv[1], dv[2], dv[3]);
        }
    }
}

// ---------------- Kernel 2: soft precision (R8/R13-proven, verbatim) ----------------
__global__ void __launch_bounds__(512) k_prec(const int* __restrict__ labels,
                                              float* __restrict__ out) {
    __shared__ float sd[4][N];
    __shared__ int   slab[N];
    __shared__ float wnum[16];
    __shared__ int   wcnt[16];
    __shared__ float swr[16];
    __shared__ int   s_done;

    const int t    = threadIdx.x;
    const int lane = t & 31;
    const int w    = t >> 5;
    const int q0   = blockIdx.x * 4;

    ((float4*)sd)[t] = __ldcg(&((const float4*)(g_D + (size_t)q0 * N))[t]);
    if (t < 128) ((int4*)slab)[t] = ((const int4*)labels)[t];
    __syncthreads();

    const int   qsel = w & 3;
    const int   q    = q0 + qsel;
    const int   lq   = slab[q];
    const float* row = sd[qsel];
    const int   jb   = (w >> 2) * 128;

    float num = 0.f;
    int   cnt = 0;
#pragma unroll
    for (int c = 0; c < 4; c++) {
        int j = jb + c * 32 + lane;
        bool f = (j != q) && (slab[j] == lq);
        unsigned bm = __ballot_sync(0xffffffffu, f);
        cnt += __popc(bm);
        while (bm) {                         // ascending j: deterministic
            int bit = __ffs(bm) - 1;
            bm &= bm - 1;
            float dj = row[jb + c * 32 + bit];
            float part = 0.f;
#pragma unroll
            for (int i = 0; i < 16; i++)
                part += sigmoid_nb((dj - row[lane + 32 * i]) * 100.0f); // 1/T2
#pragma unroll
            for (int o = 16; o; o >>= 1)
                part += __shfl_xor_sync(0xffffffffu, part, o);
            num += sigmoid_nb(5.0f - part);  // K=5, T1=1
        }
    }
    if (lane == 0) { wnum[w] = num; wcnt[w] = cnt; }
    __syncthreads();

    if (t < 4) {
        float s = wnum[t] + wnum[4 + t] + wnum[8 + t] + wnum[12 + t];
        int   c = wcnt[t] + wcnt[4 + t] + wcnt[8 + t] + wcnt[12 + t];
        g_prec[q0 + t] = s / fminf((float)c, 5.0f);  // 0/0 -> NaN like reference
    }
    __syncthreads();

    if (t == 0) {
        __threadfence();
        unsigned tk = atomicAdd(&g_ctr, 1u);
        s_done = ((tk & 127u) == 127u) ? 1 : 0;
    }
    __syncthreads();

    if (s_done) {
        __threadfence();
        float v = __ldcg(&g_prec[t]);
#pragma unroll
        for (int o = 16; o; o >>= 1)
            v += __shfl_xor_sync(0xffffffffu, v, o);
        if (lane == 0) swr[w] = v;
        __syncthreads();
        if (t == 0) {
            float s = 0.f;
#pragma unroll
            for (int i = 0; i < 16; i++) s += swr[i];
            out[0] = 1.0f - s / (float)N;
        }
    }
}

extern "C" void kernel_launch(void* const* d_in, const int* in_sizes, int n_in,
                              void* d_out, int out_size) {
    const float* emb    = (const float*)d_in[0];
    const int*   labels = (const int*)d_in[1];
    k_gram<<<128, 256>>>(emb);
    k_prec<<<128, 512>>>(labels, (float*)d_out);
}